// round 3
// baseline (speedup 1.0000x reference)
#include <cuda_runtime.h>

// Problem shapes (fixed by setup_inputs): B=4, N=2048, C=3
#define BD 4
#define NP 2048
#define NC 3
#define MM 4096          // N * (C-1) candidates per image
#define MAXDET 100

// Scratch (device globals — no allocation allowed)
__device__ float4 g_box[BD][MM];
__device__ float  g_score[BD][MM];
__device__ unsigned long long g_key[BD][MM];
__device__ float4 g_sbox[BD][MM];
__device__ float  g_sscore[BD][MM];
__device__ int    g_smeta[BD][MM];   // bit0 = valid, bit1 = label-1

__device__ __forceinline__ float read_dim(const void* p) {
    if (p == nullptr) return 800.0f;
    int v = *(const int*)p;
    if (v > 0 && v < 1000000) return (float)v;   // stored as int32
    return *(const float*)p;                      // stored as float32
}

// ---------------------------------------------------------------------------
// Kernel 1: softmax + box decode + clip + validity + sort key
// ---------------------------------------------------------------------------
__global__ void prep_kernel(const float* __restrict__ logits,
                            const float* __restrict__ reg,
                            const float* __restrict__ props,
                            const void* ph, const void* pw) {
    int tid = blockIdx.x * blockDim.x + threadIdx.x;
    if (tid >= BD * MM) return;
    int b  = tid >> 12;          // /4096
    int m  = tid & (MM - 1);
    int n  = m >> 1;
    int cc = m & 1;              // 0 or 1
    int c  = cc + 1;             // class 1 or 2 (skip background 0)

    float H = read_dim(ph), W = read_dim(pw);

    // softmax over 3 classes
    const float* L = logits + (b * NP + n) * NC;
    float l0 = L[0], l1 = L[1], l2 = L[2];
    float mx = fmaxf(l0, fmaxf(l1, l2));
    float e0 = expf(l0 - mx), e1 = expf(l1 - mx), e2 = expf(l2 - mx);
    float sc = (c == 1 ? e1 : e2) / (e0 + e1 + e2);

    // proposal geometry
    const float* P = props + (b * NP + n) * 4;
    float px1 = P[0], py1 = P[1], px2 = P[2], py2 = P[3];
    float pw_ = px2 - px1, ph_ = py2 - py1;
    float cx = px1 + 0.5f * pw_, cy = py1 + 0.5f * ph_;

    // decode with weights (10,10,5,5) and SCALE_CLAMP = ln(1000/16)
    const float* R = reg + (b * NP + n) * (4 * NC) + 4 * c;
    const float SCL = 4.135166556742356f;
    float dx = R[0] / 10.0f;
    float dy = R[1] / 10.0f;
    float dw = fminf(R[2] / 5.0f, SCL);
    float dh = fminf(R[3] / 5.0f, SCL);

    float pcx = dx * pw_ + cx;
    float pcy = dy * ph_ + cy;
    float nw  = expf(dw) * pw_;
    float nh  = expf(dh) * ph_;
    float x1 = pcx - 0.5f * nw;
    float y1 = pcy - 0.5f * nh;
    float x2 = pcx + 0.5f * nw;
    float y2 = pcy + 0.5f * nh;
    x1 = fminf(fmaxf(x1, 0.0f), W);
    x2 = fminf(fmaxf(x2, 0.0f), W);
    y1 = fminf(fmaxf(y1, 0.0f), H);
    y2 = fminf(fmaxf(y2, 0.0f), H);

    bool valid = (sc > 0.05f) && ((x2 - x1) >= 0.01f) && ((y2 - y1) >= 0.01f);

    g_box[b][m]   = make_float4(x1, y1, x2, y2);
    g_score[b][m] = sc;

    unsigned long long key;
    if (valid) {
        // score > 0 always (softmax), so monotonic map = f | signbit
        unsigned f    = __float_as_uint(sc);
        unsigned mono = f | 0x80000000u;
        key = (((unsigned long long)(~mono)) << 32) | (unsigned)m;  // asc sort -> score desc, idx asc
    } else {
        key = 0xFFFFFFFF00000000ull | (unsigned)m;                  // sorts last
    }
    g_key[b][m] = key;
}

// ---------------------------------------------------------------------------
// Kernel 2: per-image bitonic sort of 4096 keys + gather into sorted order
// ---------------------------------------------------------------------------
__global__ void sort_kernel() {
    __shared__ unsigned long long s[MM];   // 32 KB
    int b   = blockIdx.x;
    int tid = threadIdx.x;

    for (int i = tid; i < MM; i += blockDim.x) s[i] = g_key[b][i];
    __syncthreads();

    for (int k = 2; k <= MM; k <<= 1) {
        for (int j = k >> 1; j > 0; j >>= 1) {
            for (int i = tid; i < MM; i += blockDim.x) {
                int ixj = i ^ j;
                if (ixj > i) {
                    bool up = ((i & k) == 0);
                    unsigned long long a = s[i], c = s[ixj];
                    if ((a > c) == up) { s[i] = c; s[ixj] = a; }
                }
            }
            __syncthreads();
        }
    }

    // gather candidate data into sorted order for sequential NMS consumption
    for (int t = tid; t < MM; t += blockDim.x) {
        unsigned long long key = s[t];
        int idx = (int)(unsigned)key;
        g_sbox[b][t]   = g_box[b][idx];
        g_sscore[b][t] = g_score[b][idx];
        int valid = ((unsigned)(key >> 32) != 0xFFFFFFFFu) ? 1 : 0;
        g_smeta[b][t]  = valid | ((idx & 1) << 1);
    }
}

// ---------------------------------------------------------------------------
// Kernel 3: greedy NMS (warp-sequential, lane-parallel IoU) + output write
// Output layout (float32): boxes [B,100,4] | scores [B,100] | labels [B,100] | keep [B,100]
// ---------------------------------------------------------------------------
__global__ void nms_kernel(float* __restrict__ out) {
    __shared__ float4 kbox[MAXDET];
    __shared__ float  karea[MAXDET];
    __shared__ float  kscore[MAXDET];
    __shared__ int    klab[MAXDET];
    __shared__ int    s_cnt;

    int b    = blockIdx.x;
    int tid  = threadIdx.x;
    int lane = tid & 31;

    if (tid < 32) {
        int cnt = 0;
        for (int t = 0; t < MM; t++) {
            int meta = g_smeta[b][t];
            if (!(meta & 1)) break;          // sorted: all invalid at the tail
            float4 bb = g_sbox[b][t];
            int lab = (meta >> 1) & 1;
            float area = (bb.z - bb.x) * (bb.w - bb.y);

            bool sup = false;
            for (int j = lane; j < cnt; j += 32) {
                if (klab[j] == lab) {
                    float4 kb = kbox[j];
                    float ix1 = fmaxf(bb.x, kb.x);
                    float iy1 = fmaxf(bb.y, kb.y);
                    float ix2 = fminf(bb.z, kb.z);
                    float iy2 = fminf(bb.w, kb.w);
                    float iw = fmaxf(ix2 - ix1, 0.0f);
                    float ih = fmaxf(iy2 - iy1, 0.0f);
                    float inter = iw * ih;
                    float iou = inter / (area + karea[j] - inter + 1e-7f);
                    if (iou > 0.5f) sup = true;
                }
            }
            if (__ballot_sync(0xFFFFFFFFu, sup) == 0u) {
                if (lane == 0) {
                    kbox[cnt]   = bb;
                    karea[cnt]  = area;
                    kscore[cnt] = g_sscore[b][t];
                    klab[cnt]   = lab;
                }
                cnt++;
                __syncwarp();
                if (cnt == MAXDET) break;    // only first 100 kept are emitted
            }
        }
        if (lane == 0) s_cnt = cnt;
    }
    __syncthreads();

    int cnt = s_cnt;
    float* oB = out;                              // [B,100,4]
    float* oS = out + BD * MAXDET * 4;            // [B,100]
    float* oL = oS + BD * MAXDET;                 // [B,100]
    float* oK = oL + BD * MAXDET;                 // [B,100]

    for (int j = tid; j < MAXDET; j += blockDim.x) {
        bool k = (j < cnt);
        float4 bb = k ? kbox[j] : make_float4(0.f, 0.f, 0.f, 0.f);
        int base = (b * MAXDET + j) * 4;
        oB[base + 0] = bb.x;
        oB[base + 1] = bb.y;
        oB[base + 2] = bb.z;
        oB[base + 3] = bb.w;
        oS[b * MAXDET + j] = k ? kscore[j] : 0.0f;
        oL[b * MAXDET + j] = k ? (float)(klab[j] + 1) : 0.0f;
        oK[b * MAXDET + j] = k ? 1.0f : 0.0f;
    }
}

// ---------------------------------------------------------------------------
extern "C" void kernel_launch(void* const* d_in, const int* in_sizes, int n_in,
                              void* d_out, int out_size) {
    // Identify inputs by element count (all distinct) to be metadata-order robust:
    // class_logits: 4*2048*3 = 24576, box_regression: 4*2048*12 = 98304,
    // proposals: 4*2048*4 = 32768, image_h/image_w: 1 each.
    const float* logits = nullptr;
    const float* reg    = nullptr;
    const float* props  = nullptr;
    const void*  dims[2] = {nullptr, nullptr};
    int nd = 0;
    for (int i = 0; i < n_in; i++) {
        int s = in_sizes[i];
        if      (s == BD * NP * NC)     logits = (const float*)d_in[i];
        else if (s == BD * NP * 4 * NC) reg    = (const float*)d_in[i];
        else if (s == BD * NP * 4)      props  = (const float*)d_in[i];
        else if (s == 1 && nd < 2)      dims[nd++] = d_in[i];
    }

    prep_kernel<<<(BD * MM + 255) / 256, 256>>>(logits, reg, props, dims[0], dims[1]);
    sort_kernel<<<BD, 1024>>>();
    nms_kernel<<<BD, 128>>>((float*)d_out);
}

// round 4
// speedup vs baseline: 1.2103x; 1.2103x over previous
#include <cuda_runtime.h>

// Problem shapes (fixed by setup_inputs): B=4, N=2048, C=3
#define BD 4
#define NP 2048
#define NC 3
#define MM 4096          // N * (C-1) candidates per image
#define MAXDET 100
#define PRE 512          // sorted boxes pre-gathered into smem for the NMS scan

// Scratch (device global — no allocation allowed)
__device__ float4 g_box[BD][MM];

__device__ __forceinline__ float read_dim(const void* p) {
    if (p == nullptr) return 800.0f;
    int v = *(const int*)p;
    if (v > 0 && v < 1000000) return (float)v;   // stored as int32
    return *(const float*)p;                      // stored as float32
}

// ---------------------------------------------------------------------------
// Fused: softmax + decode + clip + key build -> bitonic sort (smem) ->
//        top-PRE box gather (smem) -> greedy NMS -> output write.
// One block per image, 1024 threads.
// Output layout (float32): boxes [B,100,4] | scores [B,100] | labels [B,100] | keep [B,100]
// ---------------------------------------------------------------------------
__global__ __launch_bounds__(1024, 1)
void fused_kernel(const float* __restrict__ logits,
                  const float* __restrict__ reg,
                  const float* __restrict__ props,
                  const void* ph, const void* pw,
                  float* __restrict__ out) {
    __shared__ unsigned long long s_key[MM];   // 32 KB
    __shared__ float4 s_box[PRE];              // 8 KB
    __shared__ float4 kbox[MAXDET];
    __shared__ float  karea[MAXDET];
    __shared__ float  kscore[MAXDET];
    __shared__ int    klab[MAXDET];
    __shared__ int    s_cnt;

    const int b   = blockIdx.x;
    const int tid = threadIdx.x;

    const float H = read_dim(ph), W = read_dim(pw);

    // ---- Phase A: prep (4 candidates per thread) ----
    for (int m = tid; m < MM; m += 1024) {
        int n  = m >> 1;
        int cc = m & 1;              // 0 or 1
        int c  = cc + 1;             // class 1 or 2 (skip background)

        // softmax over 3 classes
        const float* L = logits + (b * NP + n) * NC;
        float l0 = L[0], l1 = L[1], l2 = L[2];
        float mx = fmaxf(l0, fmaxf(l1, l2));
        float e0 = expf(l0 - mx), e1 = expf(l1 - mx), e2 = expf(l2 - mx);
        float sc = (c == 1 ? e1 : e2) / (e0 + e1 + e2);

        // proposal geometry
        const float4 P = *(const float4*)(props + (b * NP + n) * 4);
        float pw_ = P.z - P.x, ph_ = P.w - P.y;
        float cx = P.x + 0.5f * pw_, cy = P.y + 0.5f * ph_;

        // decode with weights (10,10,5,5), SCALE_CLAMP = ln(1000/16)
        const float* R = reg + (b * NP + n) * (4 * NC) + 4 * c;
        const float SCL = 4.135166556742356f;
        float dx = R[0] * 0.1f;
        float dy = R[1] * 0.1f;
        float dw = fminf(R[2] * 0.2f, SCL);
        float dh = fminf(R[3] * 0.2f, SCL);

        float pcx = dx * pw_ + cx;
        float pcy = dy * ph_ + cy;
        float nw  = expf(dw) * pw_;
        float nh  = expf(dh) * ph_;
        float x1 = fminf(fmaxf(pcx - 0.5f * nw, 0.0f), W);
        float y1 = fminf(fmaxf(pcy - 0.5f * nh, 0.0f), H);
        float x2 = fminf(fmaxf(pcx + 0.5f * nw, 0.0f), W);
        float y2 = fminf(fmaxf(pcy + 0.5f * nh, 0.0f), H);

        bool valid = (sc > 0.05f) && ((x2 - x1) >= 0.01f) && ((y2 - y1) >= 0.01f);

        g_box[b][m] = make_float4(x1, y1, x2, y2);

        unsigned long long key;
        if (valid) {
            unsigned f    = __float_as_uint(sc);   // sc > 0 -> mono map = f | signbit
            unsigned mono = f | 0x80000000u;
            key = (((unsigned long long)(~mono)) << 32) | (unsigned)m;  // asc -> score desc, idx asc
        } else {
            key = 0xFFFFFFFF00000000ull | (unsigned)m;                  // sorts last
        }
        s_key[m] = key;
    }
    __syncthreads();

    // ---- Phase B: bitonic sort (4096 keys, 2048 pairs, 2 pairs/thread) ----
    #pragma unroll 1
    for (int k = 2; k <= MM; k <<= 1) {
        #pragma unroll 1
        for (int j = k >> 1; j > 0; j >>= 1) {
            #pragma unroll
            for (int q = 0; q < 2; q++) {
                int p = tid + q * 1024;                       // pair index [0, 2048)
                int i = ((p & ~(j - 1)) << 1) | (p & (j - 1));
                int l = i | j;
                bool up = ((i & k) == 0);
                unsigned long long a = s_key[i], c = s_key[l];
                if ((a > c) == up) { s_key[i] = c; s_key[l] = a; }
            }
            __syncthreads();
        }
    }

    // ---- Phase C: gather top-PRE sorted boxes into smem ----
    for (int t = tid; t < PRE; t += 1024) {
        int idx = (int)(unsigned)s_key[t];
        s_box[t] = g_box[b][idx];
    }
    __syncthreads();

    // ---- Phase D: greedy NMS (warp 0 sequential, lane-parallel IoU) ----
    if (tid < 32) {
        const int lane = tid;
        int cnt = 0;
        for (int t = 0; t < MM; t++) {
            unsigned long long key = s_key[t];
            unsigned hi = (unsigned)(key >> 32);
            if (hi == 0xFFFFFFFFu) break;        // sorted: invalid tail
            int idx = (int)(unsigned)key;
            int lab = idx & 1;
            float sc = __uint_as_float((~hi) & 0x7FFFFFFFu);
            float4 bb = (t < PRE) ? s_box[t] : g_box[b][idx];
            float area = (bb.z - bb.x) * (bb.w - bb.y);

            bool sup = false;
            for (int j = lane; j < cnt; j += 32) {
                if (klab[j] == lab) {
                    float4 kb = kbox[j];
                    float iw = fminf(bb.z, kb.z) - fmaxf(bb.x, kb.x);
                    float ih = fminf(bb.w, kb.w) - fmaxf(bb.y, kb.y);
                    iw = fmaxf(iw, 0.0f);
                    ih = fmaxf(ih, 0.0f);
                    float inter = iw * ih;
                    float iou = inter / (area + karea[j] - inter + 1e-7f);
                    if (iou > 0.5f) sup = true;
                }
            }
            if (__ballot_sync(0xFFFFFFFFu, sup) == 0u) {
                if (lane == 0) {
                    kbox[cnt]   = bb;
                    karea[cnt]  = area;
                    kscore[cnt] = sc;
                    klab[cnt]   = lab;
                }
                cnt++;
                __syncwarp();
                if (cnt == MAXDET) break;        // only first 100 kept are emitted
            }
        }
        if (lane == 0) s_cnt = cnt;
    }
    __syncthreads();

    // ---- Phase E: output ----
    const int cnt = s_cnt;
    float* oB = out;                              // [B,100,4]
    float* oS = out + BD * MAXDET * 4;            // [B,100]
    float* oL = oS + BD * MAXDET;                 // [B,100]
    float* oK = oL + BD * MAXDET;                 // [B,100]

    for (int j = tid; j < MAXDET; j += 1024) {
        bool k = (j < cnt);
        float4 bb = k ? kbox[j] : make_float4(0.f, 0.f, 0.f, 0.f);
        int base = (b * MAXDET + j) * 4;
        oB[base + 0] = bb.x;
        oB[base + 1] = bb.y;
        oB[base + 2] = bb.z;
        oB[base + 3] = bb.w;
        oS[b * MAXDET + j] = k ? kscore[j] : 0.0f;
        oL[b * MAXDET + j] = k ? (float)(klab[j] + 1) : 0.0f;
        oK[b * MAXDET + j] = k ? 1.0f : 0.0f;
    }
}

// ---------------------------------------------------------------------------
extern "C" void kernel_launch(void* const* d_in, const int* in_sizes, int n_in,
                              void* d_out, int out_size) {
    // Identify inputs by element count (all distinct):
    // class_logits 24576, box_regression 98304, proposals 32768, image_h/w 1 each.
    const float* logits = nullptr;
    const float* reg    = nullptr;
    const float* props  = nullptr;
    const void*  dims[2] = {nullptr, nullptr};
    int nd = 0;
    for (int i = 0; i < n_in; i++) {
        int s = in_sizes[i];
        if      (s == BD * NP * NC)     logits = (const float*)d_in[i];
        else if (s == BD * NP * 4 * NC) reg    = (const float*)d_in[i];
        else if (s == BD * NP * 4)      props  = (const float*)d_in[i];
        else if (s == 1 && nd < 2)      dims[nd++] = d_in[i];
    }

    fused_kernel<<<BD, 1024>>>(logits, reg, props, dims[0], dims[1], (float*)d_out);
}

// round 5
// speedup vs baseline: 1.9322x; 1.5965x over previous
#include <cuda_runtime.h>

// Problem shapes (fixed by setup_inputs): B=4, N=2048, C=3
#define BD 4
#define NP 2048
#define MM 4096          // N * (C-1) candidates per image
#define MAXDET 100
#define CAP 512          // max selected candidates on the fast path
#define TSEL 256         // selection target (>> ~110 actually consumed by NMS)
#define PRE 512          // fallback: sorted boxes pre-gathered into smem

// Scratch (device global — no allocation allowed)
__device__ float4 g_box[BD][MM];

struct __align__(16) SM {
    float4 sbox[CAP];                 // selected+sorted boxes
    float4 kbox[MAXDET];              // fallback kept boxes
    unsigned long long key[MM];       // all 4096 keys (kept intact for fallback)
    unsigned long long selkey[CAP];   // selected (unordered)
    unsigned long long skey[CAP];     // selected (sorted)
    unsigned int hist[4096];
    unsigned int mask[CAP * 16];      // suppression bitmask, row-major
    unsigned int sup[128];
    float sarea[CAP];
    float karea[MAXDET];
    float kscore[MAXDET];
    int   klab[MAXDET];
    int   keptidx[MAXDET];
    unsigned char slab[CAP];
    int c1_bin, c2_bin, c_below, n_incl, n_valid, n_sel, need2, fb, s_cnt, cnt_sel;
};

__device__ __forceinline__ float read_dim(const void* p) {
    if (p == nullptr) return 800.0f;
    int v = *(const int*)p;
    if (v > 0 && v < 1000000) return (float)v;   // stored as int32
    return *(const float*)p;                      // stored as float32
}

// thread-0-only hierarchical cutoff scan over hist[0..4094] (bin 4095 = invalid).
// Finds smallest bin with cum >= target. Returns via out params.
__device__ void scan_cutoff(SM& s, int target, int& bin, int& below, int& incl, int& total) {
    // s.sup[] already holds 32-bin partial sums (sup[127] excludes bin 4095)
    total = 0;
    for (int t = 0; t < 128; t++) total += s.sup[t];
    int cum = 0, sb = -1;
    for (int t = 0; t < 128; t++) {
        if (cum + (int)s.sup[t] >= target) { sb = t; break; }
        cum += (int)s.sup[t];
    }
    if (sb < 0) { bin = 4094; below = total; incl = total; return; }
    for (int i = 0; i < 32; i++) {
        int bn = sb * 32 + i;
        if (bn == 4095) break;
        int c = (int)s.hist[bn];
        if (cum + c >= target) { bin = bn; below = cum; incl = cum + c; return; }
        cum += c;
    }
    bin = 4094; below = total; incl = total;   // unreachable safety
}

__global__ __launch_bounds__(1024, 1)
void fused_kernel(const float* __restrict__ logits,
                  const float* __restrict__ reg,
                  const float* __restrict__ props,
                  const void* ph, const void* pw,
                  float* __restrict__ out) {
    extern __shared__ unsigned char smem_raw[];
    SM& s = *reinterpret_cast<SM*>(smem_raw);

    const int b   = blockIdx.x;
    const int tid = threadIdx.x;
    const float H = read_dim(ph), W = read_dim(pw);
    const float SCL = 4.135166556742356f;   // ln(1000/16)

    if (tid == 0) { s.fb = 0; s.need2 = 0; s.cnt_sel = 0; }

    // ---- Phase A: prep. 2 proposals/thread, 2 classes each ----
    for (int p = tid; p < NP; p += 1024) {
        const float* L = logits + (b * NP + p) * 3;
        float l0 = L[0], l1 = L[1], l2 = L[2];
        float mx = fmaxf(l0, fmaxf(l1, l2));
        float e0 = expf(l0 - mx), e1 = expf(l1 - mx), e2 = expf(l2 - mx);
        float inv = 1.0f / (e0 + e1 + e2);
        float sc1 = e1 * inv, sc2 = e2 * inv;

        const float4 P = *(const float4*)(props + (b * NP + p) * 4);
        float pw_ = P.z - P.x, ph_ = P.w - P.y;
        float cx = P.x + 0.5f * pw_, cy = P.y + 0.5f * ph_;

        const float4 R1 = *(const float4*)(reg + (b * NP + p) * 12 + 4);
        const float4 R2 = *(const float4*)(reg + (b * NP + p) * 12 + 8);

        #pragma unroll
        for (int cc = 0; cc < 2; cc++) {
            float4 R = cc ? R2 : R1;
            float sc = cc ? sc2 : sc1;
            int   m  = 2 * p + cc;
            float dx = R.x * 0.1f;
            float dy = R.y * 0.1f;
            float dw = fminf(R.z * 0.2f, SCL);
            float dh = fminf(R.w * 0.2f, SCL);
            float pcx = dx * pw_ + cx;
            float pcy = dy * ph_ + cy;
            float nw  = expf(dw) * pw_;
            float nh  = expf(dh) * ph_;
            float x1 = fminf(fmaxf(pcx - 0.5f * nw, 0.0f), W);
            float y1 = fminf(fmaxf(pcy - 0.5f * nh, 0.0f), H);
            float x2 = fminf(fmaxf(pcx + 0.5f * nw, 0.0f), W);
            float y2 = fminf(fmaxf(pcy + 0.5f * nh, 0.0f), H);
            bool valid = (sc > 0.05f) && ((x2 - x1) >= 0.01f) && ((y2 - y1) >= 0.01f);
            g_box[b][m] = make_float4(x1, y1, x2, y2);
            unsigned long long key;
            if (valid) {
                unsigned mono = __float_as_uint(sc) | 0x80000000u;    // sc > 0
                key = (((unsigned long long)(~mono)) << 32) | (unsigned)m;
            } else {
                key = 0xFFFFFFFF00000000ull | (unsigned)m;            // bin 0xFFF
            }
            s.key[m] = key;
        }
    }
    __syncthreads();

    // ---- Phase B: two-pass radix select (prefix of global sorted order) ----
    for (int i = tid; i < 4096; i += 1024) s.hist[i] = 0;
    __syncthreads();
    for (int m = tid; m < MM; m += 1024)
        atomicAdd(&s.hist[(int)(s.key[m] >> 52)], 1u);
    __syncthreads();
    if (tid < 128) {
        unsigned acc = 0;
        for (int i = 0; i < 32; i++) {
            int bn = tid * 32 + i;
            if (bn != 4095) acc += s.hist[bn];
        }
        s.sup[tid] = acc;
    }
    __syncthreads();
    if (tid == 0) {
        int bin, below, incl, total;
        scan_cutoff(s, TSEL, bin, below, incl, total);
        s.c1_bin = bin; s.c_below = below; s.n_incl = incl; s.n_valid = total;
        s.need2 = (incl > CAP) ? 1 : 0;
        if (!s.need2) s.n_sel = incl;
    }
    __syncthreads();

    if (s.need2) {   // refine within cutoff bin using bits [51:40] (rare)
        int cb = s.c1_bin;
        for (int i = tid; i < 4096; i += 1024) s.hist[i] = 0;
        __syncthreads();
        for (int m = tid; m < MM; m += 1024) {
            unsigned long long k = s.key[m];
            if ((int)(k >> 52) == cb)
                atomicAdd(&s.hist[(int)(k >> 40) & 0xFFF], 1u);
        }
        __syncthreads();
        if (tid < 128) {
            unsigned acc = 0;
            for (int i = 0; i < 32; i++) acc += s.hist[tid * 32 + i];   // no invalid bin here
            s.sup[tid] = acc;
        }
        __syncthreads();
        if (tid == 0) {
            int target2 = TSEL - s.c_below;
            int cum = 0, found = -1;
            int t2 = 0;
            for (; t2 < 128; t2++) {
                if (cum + (int)s.sup[t2] >= target2) break;
                cum += (int)s.sup[t2];
            }
            if (t2 < 128) {
                for (int i = 0; i < 32; i++) {
                    int bn = t2 * 32 + i;
                    int c = (int)s.hist[bn];
                    if (cum + c >= target2) { found = bn; cum += c; break; }
                    cum += c;
                }
            }
            if (found < 0) { found = 4095; }       // take whole bin
            s.c2_bin = found;
            s.n_sel = s.c_below + cum;
            if (s.n_sel > CAP) s.fb = 1;           // pathological ties -> fallback
        }
        __syncthreads();
    }

    const bool fb1 = (s.fb != 0);
    const int n_sel = fb1 ? 0 : s.n_sel;
    const int c1b = s.c1_bin, c2b = s.c2_bin, nd2 = s.need2;

    // ---- compact selected keys (unordered) ----
    if (!fb1) {
        for (int m = tid; m < MM; m += 1024) {
            unsigned long long k = s.key[m];
            int t12 = (int)(k >> 52);
            bool sel;
            if (!nd2) sel = (t12 <= c1b);
            else      sel = (t12 < c1b) || (t12 == c1b && ((int)(k >> 40) & 0xFFF) <= c2b);
            if (sel) {
                int pos = atomicAdd(&s.cnt_sel, 1);
                s.selkey[pos] = k;
            }
        }
    }
    __syncthreads();
    if (!fb1) {
        for (int t = tid; t < CAP; t += 1024)
            if (t >= n_sel) s.selkey[t] = 0xFFFFFFFFFFFFF000ull + (unsigned)t;  // distinct sentinels
    }
    __syncthreads();

    // ---- Phase C: O(n^2) rank sort of 512 keys ----
    if (!fb1 && tid < CAP) {
        unsigned long long k = s.selkey[tid];
        int r = 0;
        #pragma unroll 8
        for (int j = 0; j < CAP; j++) r += (s.selkey[j] < k);
        s.skey[r] = k;
    }
    __syncthreads();

    // ---- Phase D: gather boxes / areas / labels for sorted selection ----
    if (!fb1 && tid < CAP) {
        if (tid < n_sel) {
            unsigned long long k = s.skey[tid];
            int idx = (int)(unsigned)k;
            float4 bb = g_box[b][idx];
            s.sbox[tid]  = bb;
            s.sarea[tid] = (bb.z - bb.x) * (bb.w - bb.y);
            s.slab[tid]  = (unsigned char)(idx & 1);
        } else {
            s.sbox[tid] = make_float4(0.f, 0.f, 0.f, 0.f);
            s.sarea[tid] = 0.f;
            s.slab[tid] = 0;
        }
    }
    __syncthreads();

    // ---- Phase E: suppression bitmask (i suppresses j>i) ----
    if (!fb1) {
        for (int u = tid; u < CAP * 16; u += 1024) {
            int i = u >> 4, w = u & 15;
            unsigned bits = 0;
            if (i < n_sel && (w * 32 + 31) > i) {
                float4 bi = s.sbox[i];
                float  ai = s.sarea[i];
                int    li = s.slab[i];
                int j0 = w * 32;
                int jend = min(32, n_sel - j0);
                for (int l = 0; l < jend; l++) {
                    int j = j0 + l;
                    if (j <= i || s.slab[j] != li) continue;
                    float4 bj = s.sbox[j];
                    float iw = fminf(bi.z, bj.z) - fmaxf(bi.x, bj.x);
                    float ih = fminf(bi.w, bj.w) - fmaxf(bi.y, bj.y);
                    iw = fmaxf(iw, 0.0f); ih = fmaxf(ih, 0.0f);
                    float inter = iw * ih;
                    // iou > 0.5  <=>  2*inter > union + 1e-7
                    if (2.0f * inter > ai + s.sarea[j] - inter + 1e-7f) bits |= (1u << l);
                }
            }
            s.mask[u] = bits;
        }
    }
    __syncthreads();

    // ---- Phase F: serial greedy resolution (warp 0, bit ops only) ----
    if (!fb1 && tid < 32) {
        unsigned removed = 0;   // lane l holds removed-word l (l < 16)
        int cnt = 0;
        for (int i = 0; i < n_sel && cnt < MAXDET; i++) {
            unsigned rw = __shfl_sync(0xFFFFFFFFu, removed, i >> 5);
            if (!((rw >> (i & 31)) & 1u)) {
                if (tid == 0) s.keptidx[cnt] = i;
                cnt++;
                if (tid < 16) removed |= s.mask[i * 16 + tid];
            }
        }
        if (tid == 0) {
            s.s_cnt = cnt;
            if (cnt < MAXDET && s.n_valid > n_sel) s.fb = 1;   // prefix exhausted
        }
    }
    __syncthreads();

    const bool fbf = (s.fb != 0);

    // ---- Phase G: output (fast path) ----
    float* oB = out;                              // [B,100,4]
    float* oS = out + BD * MAXDET * 4;            // [B,100]
    float* oL = oS + BD * MAXDET;                 // [B,100]
    float* oK = oL + BD * MAXDET;                 // [B,100]

    if (!fbf) {
        int cnt = s.s_cnt;
        for (int j = tid; j < MAXDET; j += 1024) {
            bool k = (j < cnt);
            float4 bb = make_float4(0.f, 0.f, 0.f, 0.f);
            float sc = 0.f, lb = 0.f;
            if (k) {
                int i = s.keptidx[j];
                unsigned long long key = s.skey[i];
                bb = s.sbox[i];
                sc = __uint_as_float((~(unsigned)(key >> 32)) & 0x7FFFFFFFu);
                lb = (float)(((unsigned)key & 1u) + 1u);
            }
            int base = (b * MAXDET + j) * 4;
            oB[base + 0] = bb.x; oB[base + 1] = bb.y;
            oB[base + 2] = bb.z; oB[base + 3] = bb.w;
            oS[b * MAXDET + j] = sc;
            oL[b * MAXDET + j] = lb;
            oK[b * MAXDET + j] = k ? 1.0f : 0.0f;
        }
        return;
    }

    // ================= FALLBACK: full bitonic sort + warp NMS =================
    // s.key[] is intact. (All threads are here: fb flag is block-uniform.)
    #pragma unroll 1
    for (int k = 2; k <= MM; k <<= 1) {
        #pragma unroll 1
        for (int j = k >> 1; j > 0; j >>= 1) {
            #pragma unroll
            for (int q = 0; q < 2; q++) {
                int p = tid + q * 1024;
                int i = ((p & ~(j - 1)) << 1) | (p & (j - 1));
                int l = i | j;
                bool up = ((i & k) == 0);
                unsigned long long a = s.key[i], c = s.key[l];
                if ((a > c) == up) { s.key[i] = c; s.key[l] = a; }
            }
            __syncthreads();
        }
    }
    for (int t = tid; t < PRE; t += 1024) {
        int idx = (int)(unsigned)s.key[t];
        s.sbox[t] = g_box[b][idx];
    }
    __syncthreads();

    if (tid < 32) {
        const int lane = tid;
        int cnt = 0;
        for (int t = 0; t < MM; t++) {
            unsigned long long key = s.key[t];
            unsigned hi = (unsigned)(key >> 32);
            if (hi == 0xFFFFFFFFu) break;
            int idx = (int)(unsigned)key;
            int lab = idx & 1;
            float sc = __uint_as_float((~hi) & 0x7FFFFFFFu);
            float4 bb = (t < PRE) ? s.sbox[t] : g_box[b][idx];
            float area = (bb.z - bb.x) * (bb.w - bb.y);
            bool sup = false;
            for (int j = lane; j < cnt; j += 32) {
                if (s.klab[j] == lab) {
                    float4 kb = s.kbox[j];
                    float iw = fminf(bb.z, kb.z) - fmaxf(bb.x, kb.x);
                    float ih = fminf(bb.w, kb.w) - fmaxf(bb.y, kb.y);
                    iw = fmaxf(iw, 0.0f); ih = fmaxf(ih, 0.0f);
                    float inter = iw * ih;
                    if (2.0f * inter > area + s.karea[j] - inter + 1e-7f) sup = true;
                }
            }
            if (__ballot_sync(0xFFFFFFFFu, sup) == 0u) {
                if (lane == 0) {
                    s.kbox[cnt] = bb; s.karea[cnt] = area;
                    s.kscore[cnt] = sc; s.klab[cnt] = lab;
                }
                cnt++;
                __syncwarp();
                if (cnt == MAXDET) break;
            }
        }
        if (lane == 0) s.s_cnt = cnt;
    }
    __syncthreads();

    int cnt = s.s_cnt;
    for (int j = tid; j < MAXDET; j += 1024) {
        bool k = (j < cnt);
        float4 bb = k ? s.kbox[j] : make_float4(0.f, 0.f, 0.f, 0.f);
        int base = (b * MAXDET + j) * 4;
        oB[base + 0] = bb.x; oB[base + 1] = bb.y;
        oB[base + 2] = bb.z; oB[base + 3] = bb.w;
        oS[b * MAXDET + j] = k ? s.kscore[j] : 0.0f;
        oL[b * MAXDET + j] = k ? (float)(s.klab[j] + 1) : 0.0f;
        oK[b * MAXDET + j] = k ? 1.0f : 0.0f;
    }
}

// ---------------------------------------------------------------------------
extern "C" void kernel_launch(void* const* d_in, const int* in_sizes, int n_in,
                              void* d_out, int out_size) {
    const float* logits = nullptr;
    const float* reg    = nullptr;
    const float* props  = nullptr;
    const void*  dims[2] = {nullptr, nullptr};
    int nd = 0;
    for (int i = 0; i < n_in; i++) {
        int sz = in_sizes[i];
        if      (sz == BD * NP * 3)  logits = (const float*)d_in[i];
        else if (sz == BD * NP * 12) reg    = (const float*)d_in[i];
        else if (sz == BD * NP * 4)  props  = (const float*)d_in[i];
        else if (sz == 1 && nd < 2)  dims[nd++] = d_in[i];
    }

    const int smem_bytes = (int)sizeof(SM);
    cudaFuncSetAttribute(fused_kernel, cudaFuncAttributeMaxDynamicSharedMemorySize, smem_bytes);
    fused_kernel<<<BD, 1024, smem_bytes>>>(logits, reg, props, dims[0], dims[1], (float*)d_out);
}

// round 6
// speedup vs baseline: 2.8329x; 1.4662x over previous
#include <cuda_runtime.h>

// Problem shapes (fixed by setup_inputs): B=4, N=2048, C=3
#define BD 4
#define NP 2048
#define MM 4096          // N * (C-1) candidates per image
#define MAXDET 100
#define CAP 512          // max selected candidates (global prefix)
#define PCCAP 256        // max per-class selected candidates
#define TSEL 256         // selection target (>> ~110 consumed by NMS)
#define PRE 512          // fallback: sorted boxes pre-gathered into smem

// Scratch (device global — no allocation allowed)
__device__ float4 g_box[BD][MM];

struct __align__(16) SM {
    unsigned long long key[MM];       // all 4096 keys (intact for fallback)
    unsigned long long selkey[CAP];   // selected (unordered, padded)
    unsigned long long skey[CAP];     // selected (sorted)
    float4 sbox[CAP];                 // boxes in global sorted order
    float4 cbox[2][PCCAP];            // per-class boxes (score order, zero-padded)
    float4 kbox[MAXDET];              // fallback kept boxes
    unsigned int hist[4096];
    unsigned int mask[2][PCCAP][8];   // per-class suppression bitmask
    float carea[2][PCCAP];
    unsigned int sup[128];
    unsigned int labw[16];            // label-1 bit per global rank
    unsigned int pre1[16];            // excl prefix of label-1 popcounts
    unsigned int kbits[2][8];         // per-class keep bits
    unsigned int kw[16];              // global keep bits
    unsigned int kpre[16];            // excl prefix of keep popcounts
    unsigned short clsrank[CAP];
    float karea[MAXDET]; float kscore[MAXDET]; int klab[MAXDET];
    int cn[2];
    int c1_bin, n_valid, n_sel, fb, s_cnt, cnt_sel, kept_total;
};

__device__ __forceinline__ float read_dim(const void* p) {
    if (p == nullptr) return 800.0f;
    int v = *(const int*)p;
    if (v > 0 && v < 1000000) return (float)v;   // stored as int32
    return *(const float*)p;                      // stored as float32
}

__global__ __launch_bounds__(1024, 1)
void fused_kernel(const float* __restrict__ logits,
                  const float* __restrict__ reg,
                  const float* __restrict__ props,
                  const void* ph, const void* pw,
                  float* __restrict__ out) {
    extern __shared__ unsigned char smem_raw[];
    SM& s = *reinterpret_cast<SM*>(smem_raw);

    const int b    = blockIdx.x;
    const int tid  = threadIdx.x;
    const int lane = tid & 31;
    const int wid  = tid >> 5;
    const unsigned FULL = 0xFFFFFFFFu;
    const float H = read_dim(ph), W = read_dim(pw);
    const float SCL = 4.135166556742356f;   // ln(1000/16)

    if (tid == 0) { s.fb = 0; s.cnt_sel = 0; s.n_sel = 0; }

    // ---- Phase A: prep (softmax + decode + clip + key) ----
    for (int p = tid; p < NP; p += 1024) {
        const float* L = logits + (b * NP + p) * 3;
        float l0 = L[0], l1 = L[1], l2 = L[2];
        float mx = fmaxf(l0, fmaxf(l1, l2));
        float e0 = expf(l0 - mx), e1 = expf(l1 - mx), e2 = expf(l2 - mx);
        float inv = 1.0f / (e0 + e1 + e2);
        float sc1 = e1 * inv, sc2 = e2 * inv;

        const float4 P = *(const float4*)(props + (b * NP + p) * 4);
        float pw_ = P.z - P.x, ph_ = P.w - P.y;
        float cx = P.x + 0.5f * pw_, cy = P.y + 0.5f * ph_;

        const float4 R1 = *(const float4*)(reg + (b * NP + p) * 12 + 4);
        const float4 R2 = *(const float4*)(reg + (b * NP + p) * 12 + 8);

        #pragma unroll
        for (int cc = 0; cc < 2; cc++) {
            float4 R = cc ? R2 : R1;
            float sc = cc ? sc2 : sc1;
            int   m  = 2 * p + cc;
            float dx = R.x * 0.1f;
            float dy = R.y * 0.1f;
            float dw = fminf(R.z * 0.2f, SCL);
            float dh = fminf(R.w * 0.2f, SCL);
            float pcx = dx * pw_ + cx;
            float pcy = dy * ph_ + cy;
            float nw  = expf(dw) * pw_;
            float nh  = expf(dh) * ph_;
            float x1 = fminf(fmaxf(pcx - 0.5f * nw, 0.0f), W);
            float y1 = fminf(fmaxf(pcy - 0.5f * nh, 0.0f), H);
            float x2 = fminf(fmaxf(pcx + 0.5f * nw, 0.0f), W);
            float y2 = fminf(fmaxf(pcy + 0.5f * nh, 0.0f), H);
            bool valid = (sc > 0.05f) && ((x2 - x1) >= 0.01f) && ((y2 - y1) >= 0.01f);
            g_box[b][m] = make_float4(x1, y1, x2, y2);
            unsigned long long key;
            if (valid) {
                unsigned mono = __float_as_uint(sc) | 0x80000000u;    // sc > 0
                key = (((unsigned long long)(~mono)) << 32) | (unsigned)m;
            } else {
                key = 0xFFFFFFFF00000000ull | (unsigned)m;            // bin 0xFFF
            }
            s.key[m] = key;
        }
    }
    __syncthreads();

    // ---- Phase B: 12-bit histogram + cutoff (prefix of global sorted order) ----
    for (int i = tid; i < 4096; i += 1024) s.hist[i] = 0;
    __syncthreads();
    for (int m = tid; m < MM; m += 1024)
        atomicAdd(&s.hist[(int)(s.key[m] >> 52)], 1u);
    __syncthreads();
    if (tid < 128) {
        unsigned acc = 0;
        #pragma unroll
        for (int i = 0; i < 32; i++) {
            int bn = tid * 32 + i;
            if (bn != 4095) acc += s.hist[bn];
        }
        s.sup[tid] = acc;
    }
    __syncthreads();
    if (tid < 32) {   // warp-parallel cutoff scan
        unsigned v0 = s.sup[lane * 4 + 0], v1 = s.sup[lane * 4 + 1];
        unsigned v2 = s.sup[lane * 4 + 2], v3 = s.sup[lane * 4 + 3];
        unsigned lsum = v0 + v1 + v2 + v3;
        unsigned inc = lsum;
        #pragma unroll
        for (int o = 1; o < 32; o <<= 1) {
            unsigned x = __shfl_up_sync(FULL, inc, o);
            if (lane >= o) inc += x;
        }
        unsigned excl = inc - lsum;
        unsigned total = __shfl_sync(FULL, inc, 31);
        bool cross = ((int)excl < TSEL) && ((int)(excl + lsum) >= TSEL);
        unsigned mb = __ballot_sync(FULL, cross);
        if (mb == 0) {
            if (lane == 0) {          // fewer than TSEL valid -> take all
                s.c1_bin = 4094; s.n_valid = (int)total; s.n_sel = (int)total;
            }
        } else {
            int src = __ffs(mb) - 1;
            if (lane == src) {
                int cum = (int)excl;
                unsigned vv[4] = {v0, v1, v2, v3};
                int chunk = src * 4;
                #pragma unroll
                for (int q = 0; q < 4; q++) {
                    if (cum + (int)vv[q] >= TSEL) { chunk = src * 4 + q; break; }
                    cum += (int)vv[q];
                }
                int bin = 4094, incl = cum;
                for (int i2 = 0; i2 < 32; i2++) {
                    int bn = chunk * 32 + i2;
                    if (bn == 4095) break;
                    int c = (int)s.hist[bn];
                    if (cum + c >= TSEL) { bin = bn; incl = cum + c; break; }
                    cum += c;
                }
                s.c1_bin = bin; s.n_valid = (int)total;
                if (incl > CAP) s.fb = 1;   // fat cutoff bin -> fallback
                else            s.n_sel = incl;
            }
        }
    }
    __syncthreads();

    const int n_sel = s.n_sel;
    const int c1b   = s.c1_bin;

    // ---- compact selected keys (unordered) ----
    if (!s.fb) {
        for (int m = tid; m < MM; m += 1024) {
            unsigned long long k = s.key[m];
            if ((int)(k >> 52) <= c1b) {
                int pos = atomicAdd(&s.cnt_sel, 1);
                if (pos < CAP) s.selkey[pos] = k;
            }
        }
    }
    __syncthreads();
    for (int t = tid; t < CAP; t += 1024)
        if (t >= n_sel) s.selkey[t] = 0xFFFFFFFFFFFFF000ull + (unsigned)t;
    __syncthreads();

    // ---- Phase C: rank sort (padded trip count) ----
    const int n_pad = (n_sel + 31) & ~31;
    if (tid < n_pad) {
        unsigned long long k = s.selkey[tid];
        int r = 0;
        #pragma unroll 8
        for (int j = 0; j < n_pad; j++) r += (s.selkey[j] < k);
        s.skey[r] = k;
    }
    __syncthreads();

    // ---- Phase D: gather + per-class partition ----
    bool act = false; int lab = 0; float4 bb = make_float4(0.f, 0.f, 0.f, 0.f);
    if (tid < 512) {
        act = (tid < n_sel);
        if (act) {
            int idx = (int)(unsigned)s.skey[tid];
            lab = idx & 1;
            bb = g_box[b][idx];
            s.sbox[tid] = bb;
        }
        unsigned bal = __ballot_sync(FULL, act && lab);
        if (lane == 0) s.labw[wid] = bal;
    }
    __syncthreads();
    if (tid < 32) {
        unsigned c = (lane < 16) ? __popc(s.labw[lane]) : 0;
        unsigned inc = c;
        #pragma unroll
        for (int o = 1; o < 32; o <<= 1) {
            unsigned x = __shfl_up_sync(FULL, inc, o);
            if (lane >= o) inc += x;
        }
        if (lane < 16) s.pre1[lane] = inc - c;
        unsigned cn1 = __shfl_sync(FULL, inc, 15);
        if (lane == 0) {
            s.cn[1] = (int)cn1;
            s.cn[0] = n_sel - (int)cn1;
            if (s.cn[0] > PCCAP || s.cn[1] > PCCAP) s.fb = 1;
        }
    }
    __syncthreads();
    if (tid < 512 && act) {
        unsigned low = (1u << lane) - 1u;
        int c1below = (int)s.pre1[wid] + __popc(s.labw[wid] & low);
        int r = lab ? c1below : (tid - c1below);
        s.clsrank[tid] = (unsigned short)r;
        if (r < PCCAP) {
            s.cbox[lab][r]  = bb;
            s.carea[lab][r] = (bb.z - bb.x) * (bb.w - bb.y);
        }
    }
    // zero-pad per-class tails (disjoint addresses from scatter above)
    for (int u = tid; u < 2 * PCCAP; u += 1024) {
        int c = u >> 8, r = u & (PCCAP - 1);
        if (r >= min(s.cn[c], PCCAP)) {
            s.cbox[c][r] = make_float4(0.f, 0.f, 0.f, 0.f);
            s.carea[c][r] = 0.f;
        }
    }
    __syncthreads();

    // ---- Phase E: per-class suppression bitmask ----
    for (int u = tid; u < 2 * PCCAP * 8; u += 1024) {
        int c = u >> 11, i = (u >> 3) & (PCCAP - 1), w = u & 7;
        unsigned bits = 0;
        int nc_ = s.cn[c];
        if (i < nc_ && w >= (i >> 5) && (w << 5) < nc_) {
            float4 bi = s.cbox[c][i];
            float  ai = s.carea[c][i];
            int j0 = w << 5;
            #pragma unroll
            for (int l = 0; l < 32; l++) {
                int j = j0 + l;
                float4 bj = s.cbox[c][j];
                float iw = fminf(bi.z, bj.z) - fmaxf(bi.x, bj.x);
                float ih = fminf(bi.w, bj.w) - fmaxf(bi.y, bj.y);
                iw = fmaxf(iw, 0.0f); ih = fmaxf(ih, 0.0f);
                float inter = iw * ih;
                bool sp = (j > i) && (2.0f * inter > ai + s.carea[c][j] - inter + 1e-7f);
                bits |= (sp ? (1u << l) : 0u);
            }
        }
        s.mask[c][i][w] = bits;
    }
    __syncthreads();

    // ---- Phase F: per-class greedy resolution (warps 0 and 1 in parallel) ----
    if (wid < 2) {
        int c = wid;
        int nc_ = min(s.cn[c], PCCAP);
        unsigned removed = 0, kb = 0;
        int cnt = 0;
        for (int i = 0; i < nc_; i++) {
            unsigned rw = __shfl_sync(FULL, removed, i >> 5);
            if (!((rw >> (i & 31)) & 1u)) {
                if (lane == (i >> 5)) kb |= 1u << (i & 31);
                cnt++;
                if (lane < 8) removed |= s.mask[c][i][lane];
                if (cnt == MAXDET) break;
            }
        }
        if (lane < 8) s.kbits[c][lane] = kb;
    }
    __syncthreads();

    // ---- Phase G: merge kept flags back to global order ----
    bool kflag = false;
    if (tid < 512) {
        if (act) {
            int r = s.clsrank[tid];
            kflag = (s.kbits[lab][r >> 5] >> (r & 31)) & 1u;
        }
        unsigned bal = __ballot_sync(FULL, kflag);
        if (lane == 0) s.kw[wid] = bal;
    }
    __syncthreads();
    if (tid < 32) {
        unsigned c = (lane < 16) ? __popc(s.kw[lane]) : 0;
        unsigned inc = c;
        #pragma unroll
        for (int o = 1; o < 32; o <<= 1) {
            unsigned x = __shfl_up_sync(FULL, inc, o);
            if (lane >= o) inc += x;
        }
        if (lane < 16) s.kpre[lane] = inc - c;
        unsigned tot = __shfl_sync(FULL, inc, 15);
        if (lane == 0) {
            s.kept_total = (int)tot;
            if ((int)tot < MAXDET && s.n_valid > n_sel) s.fb = 1;  // prefix exhausted
        }
    }
    __syncthreads();

    float* oB = out;                              // [B,100,4]
    float* oS = out + BD * MAXDET * 4;            // [B,100]
    float* oL = oS + BD * MAXDET;                 // [B,100]
    float* oK = oL + BD * MAXDET;                 // [B,100]

    if (!s.fb) {
        // default zero-fill, then scatter kept rows
        for (int j = tid; j < MAXDET; j += 1024) {
            int base = (b * MAXDET + j) * 4;
            oB[base + 0] = 0.f; oB[base + 1] = 0.f; oB[base + 2] = 0.f; oB[base + 3] = 0.f;
            oS[b * MAXDET + j] = 0.f;
            oL[b * MAXDET + j] = 0.f;
            oK[b * MAXDET + j] = 0.f;
        }
        __syncthreads();
        if (tid < 512 && kflag) {
            unsigned low = (1u << lane) - 1u;
            int pos = (int)s.kpre[wid] + __popc(s.kw[wid] & low);
            if (pos < MAXDET) {
                unsigned long long key = s.skey[tid];
                float sc = __uint_as_float((~(unsigned)(key >> 32)) & 0x7FFFFFFFu);
                float4 bx = s.sbox[tid];
                int base = (b * MAXDET + pos) * 4;
                oB[base + 0] = bx.x; oB[base + 1] = bx.y;
                oB[base + 2] = bx.z; oB[base + 3] = bx.w;
                oS[b * MAXDET + pos] = sc;
                oL[b * MAXDET + pos] = (float)(lab + 1);
                oK[b * MAXDET + pos] = 1.0f;
            }
        }
        return;
    }

    // ================= FALLBACK: full bitonic sort + warp NMS =================
    #pragma unroll 1
    for (int k = 2; k <= MM; k <<= 1) {
        #pragma unroll 1
        for (int j = k >> 1; j > 0; j >>= 1) {
            #pragma unroll
            for (int q = 0; q < 2; q++) {
                int p = tid + q * 1024;
                int i = ((p & ~(j - 1)) << 1) | (p & (j - 1));
                int l = i | j;
                bool up = ((i & k) == 0);
                unsigned long long a = s.key[i], c = s.key[l];
                if ((a > c) == up) { s.key[i] = c; s.key[l] = a; }
            }
            __syncthreads();
        }
    }
    for (int t = tid; t < PRE; t += 1024) {
        int idx = (int)(unsigned)s.key[t];
        s.sbox[t] = g_box[b][idx];
    }
    __syncthreads();

    if (tid < 32) {
        int cnt = 0;
        for (int t = 0; t < MM; t++) {
            unsigned long long key = s.key[t];
            unsigned hi = (unsigned)(key >> 32);
            if (hi == 0xFFFFFFFFu) break;
            int idx = (int)(unsigned)key;
            int lb = idx & 1;
            float sc = __uint_as_float((~hi) & 0x7FFFFFFFu);
            float4 bc = (t < PRE) ? s.sbox[t] : g_box[b][idx];
            float area = (bc.z - bc.x) * (bc.w - bc.y);
            bool sup = false;
            for (int j = lane; j < cnt; j += 32) {
                if (s.klab[j] == lb) {
                    float4 kb = s.kbox[j];
                    float iw = fminf(bc.z, kb.z) - fmaxf(bc.x, kb.x);
                    float ih = fminf(bc.w, kb.w) - fmaxf(bc.y, kb.y);
                    iw = fmaxf(iw, 0.0f); ih = fmaxf(ih, 0.0f);
                    float inter = iw * ih;
                    if (2.0f * inter > area + s.karea[j] - inter + 1e-7f) sup = true;
                }
            }
            if (__ballot_sync(FULL, sup) == 0u) {
                if (lane == 0) {
                    s.kbox[cnt] = bc; s.karea[cnt] = area;
                    s.kscore[cnt] = sc; s.klab[cnt] = lb;
                }
                cnt++;
                __syncwarp();
                if (cnt == MAXDET) break;
            }
        }
        if (lane == 0) s.s_cnt = cnt;
    }
    __syncthreads();

    int cnt = s.s_cnt;
    for (int j = tid; j < MAXDET; j += 1024) {
        bool k = (j < cnt);
        float4 bc = k ? s.kbox[j] : make_float4(0.f, 0.f, 0.f, 0.f);
        int base = (b * MAXDET + j) * 4;
        oB[base + 0] = bc.x; oB[base + 1] = bc.y;
        oB[base + 2] = bc.z; oB[base + 3] = bc.w;
        oS[b * MAXDET + j] = k ? s.kscore[j] : 0.0f;
        oL[b * MAXDET + j] = k ? (float)(s.klab[j] + 1) : 0.0f;
        oK[b * MAXDET + j] = k ? 1.0f : 0.0f;
    }
}

// ---------------------------------------------------------------------------
extern "C" void kernel_launch(void* const* d_in, const int* in_sizes, int n_in,
                              void* d_out, int out_size) {
    const float* logits = nullptr;
    const float* reg    = nullptr;
    const float* props  = nullptr;
    const void*  dims[2] = {nullptr, nullptr};
    int nd = 0;
    for (int i = 0; i < n_in; i++) {
        int sz = in_sizes[i];
        if      (sz == BD * NP * 3)  logits = (const float*)d_in[i];
        else if (sz == BD * NP * 12) reg    = (const float*)d_in[i];
        else if (sz == BD * NP * 4)  props  = (const float*)d_in[i];
        else if (sz == 1 && nd < 2)  dims[nd++] = d_in[i];
    }

    const int smem_bytes = (int)sizeof(SM);
    cudaFuncSetAttribute(fused_kernel, cudaFuncAttributeMaxDynamicSharedMemorySize, smem_bytes);
    fused_kernel<<<BD, 1024, smem_bytes>>>(logits, reg, props, dims[0], dims[1], (float*)d_out);
}

// round 7
// speedup vs baseline: 2.9301x; 1.0343x over previous
#include <cuda_runtime.h>

// Problem shapes (fixed by setup_inputs): B=4, N=2048, C=3
#define BD 4
#define NP 2048
#define MM 4096          // N * (C-1) candidates per image
#define MAXDET 100
#define CAP 512          // max selected candidates (global prefix)
#define PCCAP 256        // max per-class selected candidates
#define TSEL 256         // selection target (>> ~110 consumed by NMS)
#define PRE 512          // fallback: sorted boxes pre-gathered into smem
#define HB0 0x400        // first histogram bin (12-bit key bin space)
#define NHB 64           // histogram bins

// Scratch (device global — no allocation allowed)
__device__ float4 g_box[BD][MM];

struct __align__(16) SM {
    unsigned long long key[MM];       // all 4096 keys (intact for fallback)
    unsigned long long selkey[CAP];   // selected (unordered, padded)
    unsigned long long skey[CAP];     // selected (sorted)
    float4 sbox[CAP];                 // boxes in global sorted order
    float4 cbox[2][PCCAP];            // per-class boxes (score order, zero-padded)
    float4 kbox[MAXDET];              // fallback kept boxes
    unsigned int hist[NHB];
    unsigned int mask[2][PCCAP][8];   // per-class suppression bitmask
    float carea[2][PCCAP];
    unsigned int labw[16];            // label-1 bit per global rank
    unsigned int pre1[16];            // excl prefix of label-1 popcounts
    unsigned int kbits[2][8];         // per-class keep bits
    unsigned int kw[16];              // global keep bits
    unsigned int kpre[16];            // excl prefix of keep popcounts
    unsigned short clsrank[CAP];
    float karea[MAXDET]; float kscore[MAXDET]; int klab[MAXDET];
    int cn[2];
    int c1_rel, n_valid, n_sel, fb, s_cnt, cnt_sel, kept_total;
};

__device__ __forceinline__ float read_dim(const void* p) {
    if (p == nullptr) return 800.0f;
    int v = *(const int*)p;
    if (v > 0 && v < 1000000) return (float)v;   // stored as int32
    return *(const float*)p;                      // stored as float32
}

__device__ __forceinline__ int hbin_of(unsigned long long k) {
    int b12 = (int)(k >> 52);
    return min(max(b12 - HB0, 0), NHB - 1);
}

__global__ __launch_bounds__(1024, 1)
void fused_kernel(const float* __restrict__ logits,
                  const float* __restrict__ reg,
                  const float* __restrict__ props,
                  const void* ph, const void* pw,
                  float* __restrict__ out) {
    extern __shared__ unsigned char smem_raw[];
    SM& s = *reinterpret_cast<SM*>(smem_raw);

    const int b    = blockIdx.x;
    const int tid  = threadIdx.x;
    const int lane = tid & 31;
    const int wid  = tid >> 5;
    const unsigned FULL = 0xFFFFFFFFu;
    const float H = read_dim(ph), W = read_dim(pw);
    const float SCL = 4.135166556742356f;   // ln(1000/16)

    if (tid == 0) { s.fb = 0; s.cnt_sel = 0; s.n_sel = 0; }
    if (tid < NHB) s.hist[tid] = 0;

    // ---- Phase A: prep (softmax + decode + clip + key) ----
    for (int p = tid; p < NP; p += 1024) {
        const float* L = logits + (b * NP + p) * 3;
        float l0 = L[0], l1 = L[1], l2 = L[2];
        float mx = fmaxf(l0, fmaxf(l1, l2));
        float e0 = __expf(l0 - mx), e1 = __expf(l1 - mx), e2 = __expf(l2 - mx);
        float inv = __fdividef(1.0f, e0 + e1 + e2);
        float sc1 = e1 * inv, sc2 = e2 * inv;

        const float4 P = *(const float4*)(props + (b * NP + p) * 4);
        float pw_ = P.z - P.x, ph_ = P.w - P.y;
        float cx = P.x + 0.5f * pw_, cy = P.y + 0.5f * ph_;

        const float4 R1 = *(const float4*)(reg + (b * NP + p) * 12 + 4);
        const float4 R2 = *(const float4*)(reg + (b * NP + p) * 12 + 8);

        #pragma unroll
        for (int cc = 0; cc < 2; cc++) {
            float4 R = cc ? R2 : R1;
            float sc = cc ? sc2 : sc1;
            int   m  = 2 * p + cc;
            float dx = R.x * 0.1f;
            float dy = R.y * 0.1f;
            float dw = fminf(R.z * 0.2f, SCL);
            float dh = fminf(R.w * 0.2f, SCL);
            float pcx = dx * pw_ + cx;
            float pcy = dy * ph_ + cy;
            float nw  = __expf(dw) * pw_;
            float nh  = __expf(dh) * ph_;
            float x1 = fminf(fmaxf(pcx - 0.5f * nw, 0.0f), W);
            float y1 = fminf(fmaxf(pcy - 0.5f * nh, 0.0f), H);
            float x2 = fminf(fmaxf(pcx + 0.5f * nw, 0.0f), W);
            float y2 = fminf(fmaxf(pcy + 0.5f * nh, 0.0f), H);
            bool valid = (sc > 0.05f) && ((x2 - x1) >= 0.01f) && ((y2 - y1) >= 0.01f);
            g_box[b][m] = make_float4(x1, y1, x2, y2);
            unsigned long long key;
            if (valid) {
                unsigned mono = __float_as_uint(sc) | 0x80000000u;    // sc > 0
                key = (((unsigned long long)(~mono)) << 32) | (unsigned)m;
            } else {
                key = 0xFFFFFFFF00000000ull | (unsigned)m;            // bin 0xFFF
            }
            s.key[m] = key;
        }
    }
    __syncthreads();

    // ---- Phase B: compact 64-bin histogram + single-warp cutoff scan ----
    for (int m = tid; m < MM; m += 1024) {
        unsigned long long k = s.key[m];
        if ((int)(k >> 52) != 0xFFF)
            atomicAdd(&s.hist[hbin_of(k)], 1u);
    }
    __syncthreads();
    if (tid < 32) {   // 2 bins per lane, ordered scan
        unsigned v0 = s.hist[2 * lane], v1 = s.hist[2 * lane + 1];
        unsigned lsum = v0 + v1;
        unsigned inc = lsum;
        #pragma unroll
        for (int o = 1; o < 32; o <<= 1) {
            unsigned x = __shfl_up_sync(FULL, inc, o);
            if (lane >= o) inc += x;
        }
        unsigned excl = inc - lsum;
        unsigned total = __shfl_sync(FULL, inc, 31);
        bool cross = ((int)excl < TSEL) && ((int)(excl + lsum) >= TSEL);
        unsigned mb = __ballot_sync(FULL, cross);
        if (lane == 0) s.n_valid = (int)total;
        if (mb == 0) {
            if (lane == 0) { s.c1_rel = NHB - 1; s.n_sel = (int)total; }  // take all valid
        } else {
            int src = __ffs(mb) - 1;
            if (lane == src) {
                int rel, incl;
                if ((int)excl + (int)v0 >= TSEL) { rel = 2 * src;     incl = (int)excl + (int)v0; }
                else                             { rel = 2 * src + 1; incl = (int)excl + (int)lsum; }
                if (incl > CAP) s.fb = 1;                      // fat cutoff bin -> fallback
                else            { s.c1_rel = rel; s.n_sel = incl; }
            }
        }
    }
    __syncthreads();

    const int n_sel = s.n_sel;
    const int c1r   = s.c1_rel;

    // ---- compact selected keys (unordered) ----
    if (!s.fb) {
        for (int m = tid; m < MM; m += 1024) {
            unsigned long long k = s.key[m];
            if ((int)(k >> 52) != 0xFFF && hbin_of(k) <= c1r) {
                int pos = atomicAdd(&s.cnt_sel, 1);
                if (pos < CAP) s.selkey[pos] = k;
            }
        }
    }
    __syncthreads();
    for (int t = tid; t < CAP; t += 1024)
        if (t >= n_sel) s.selkey[t] = 0xFFFFFFFFFFFFF000ull + (unsigned)t;
    __syncthreads();

    // ---- Phase C: rank sort (padded trip count) ----
    const int n_pad = (n_sel + 31) & ~31;
    if (tid < n_pad) {
        unsigned long long k = s.selkey[tid];
        int r = 0;
        #pragma unroll 8
        for (int j = 0; j < n_pad; j++) r += (s.selkey[j] < k);
        s.skey[r] = k;
    }
    __syncthreads();

    // ---- Phase D: gather + per-class partition ----
    bool act = false; int lab = 0; float4 bb = make_float4(0.f, 0.f, 0.f, 0.f);
    if (tid < 512) {
        act = (tid < n_sel);
        if (act) {
            int idx = (int)(unsigned)s.skey[tid];
            lab = idx & 1;
            bb = g_box[b][idx];
            s.sbox[tid] = bb;
        }
        unsigned bal = __ballot_sync(FULL, act && lab);
        if (lane == 0) s.labw[wid] = bal;
    }
    __syncthreads();
    if (tid < 32) {
        unsigned c = (lane < 16) ? __popc(s.labw[lane]) : 0;
        unsigned inc = c;
        #pragma unroll
        for (int o = 1; o < 32; o <<= 1) {
            unsigned x = __shfl_up_sync(FULL, inc, o);
            if (lane >= o) inc += x;
        }
        if (lane < 16) s.pre1[lane] = inc - c;
        unsigned cn1 = __shfl_sync(FULL, inc, 15);
        if (lane == 0) {
            s.cn[1] = (int)cn1;
            s.cn[0] = n_sel - (int)cn1;
            if (s.cn[0] > PCCAP || s.cn[1] > PCCAP) s.fb = 1;
        }
    }
    __syncthreads();
    if (tid < 512 && act) {
        unsigned low = (1u << lane) - 1u;
        int c1below = (int)s.pre1[wid] + __popc(s.labw[wid] & low);
        int r = lab ? c1below : (tid - c1below);
        s.clsrank[tid] = (unsigned short)r;
        if (r < PCCAP) {
            s.cbox[lab][r]  = bb;
            s.carea[lab][r] = (bb.z - bb.x) * (bb.w - bb.y);
        }
    }
    // zero-pad per-class tails (disjoint addresses from scatter above)
    for (int u = tid; u < 2 * PCCAP; u += 1024) {
        int c = u >> 8, r = u & (PCCAP - 1);
        if (r >= min(s.cn[c], PCCAP)) {
            s.cbox[c][r] = make_float4(0.f, 0.f, 0.f, 0.f);
            s.carea[c][r] = 0.f;
        }
    }
    __syncthreads();

    // ---- Phase E: per-class suppression bitmask ----
    for (int u = tid; u < 2 * PCCAP * 8; u += 1024) {
        int c = u >> 11, i = (u >> 3) & (PCCAP - 1), w = u & 7;
        unsigned bits = 0;
        int nc_ = s.cn[c];
        if (i < nc_ && w >= (i >> 5) && (w << 5) < nc_) {
            float4 bi = s.cbox[c][i];
            float  ai = s.carea[c][i];
            int j0 = w << 5;
            #pragma unroll
            for (int l = 0; l < 32; l++) {
                int j = j0 + l;
                float4 bj = s.cbox[c][j];
                float iw = fminf(bi.z, bj.z) - fmaxf(bi.x, bj.x);
                float ih = fminf(bi.w, bj.w) - fmaxf(bi.y, bj.y);
                iw = fmaxf(iw, 0.0f); ih = fmaxf(ih, 0.0f);
                float inter = iw * ih;
                bool sp = (j > i) && (2.0f * inter > ai + s.carea[c][j] - inter + 1e-7f);
                bits |= (sp ? (1u << l) : 0u);
            }
        }
        s.mask[c][i][w] = bits;
    }
    __syncthreads();

    // ---- Phase F: per-class greedy resolution (warps 0 and 1 in parallel) ----
    if (wid < 2) {
        int c = wid;
        int nc_ = min(s.cn[c], PCCAP);
        unsigned removed = 0, kb = 0;
        int cnt = 0;
        for (int i = 0; i < nc_; i++) {
            unsigned rw = __shfl_sync(FULL, removed, i >> 5);
            if (!((rw >> (i & 31)) & 1u)) {
                if (lane == (i >> 5)) kb |= 1u << (i & 31);
                cnt++;
                if (lane < 8) removed |= s.mask[c][i][lane];
                if (cnt == MAXDET) break;
            }
        }
        if (lane < 8) s.kbits[c][lane] = kb;
    }
    __syncthreads();

    // ---- Phase G: merge kept flags back to global order ----
    bool kflag = false;
    if (tid < 512) {
        if (act) {
            int r = s.clsrank[tid];
            kflag = (s.kbits[lab][r >> 5] >> (r & 31)) & 1u;
        }
        unsigned bal = __ballot_sync(FULL, kflag);
        if (lane == 0) s.kw[wid] = bal;
    }
    __syncthreads();
    if (tid < 32) {
        unsigned c = (lane < 16) ? __popc(s.kw[lane]) : 0;
        unsigned inc = c;
        #pragma unroll
        for (int o = 1; o < 32; o <<= 1) {
            unsigned x = __shfl_up_sync(FULL, inc, o);
            if (lane >= o) inc += x;
        }
        if (lane < 16) s.kpre[lane] = inc - c;
        unsigned tot = __shfl_sync(FULL, inc, 15);
        if (lane == 0) {
            s.kept_total = (int)tot;
            if ((int)tot < MAXDET && s.n_valid > n_sel) s.fb = 1;  // prefix exhausted
        }
    }
    __syncthreads();

    float* oB = out;                              // [B,100,4]
    float* oS = out + BD * MAXDET * 4;            // [B,100]
    float* oL = oS + BD * MAXDET;                 // [B,100]
    float* oK = oL + BD * MAXDET;                 // [B,100]

    if (!s.fb) {
        for (int j = tid; j < MAXDET; j += 1024) {
            int base = (b * MAXDET + j) * 4;
            oB[base + 0] = 0.f; oB[base + 1] = 0.f; oB[base + 2] = 0.f; oB[base + 3] = 0.f;
            oS[b * MAXDET + j] = 0.f;
            oL[b * MAXDET + j] = 0.f;
            oK[b * MAXDET + j] = 0.f;
        }
        __syncthreads();
        if (tid < 512 && kflag) {
            unsigned low = (1u << lane) - 1u;
            int pos = (int)s.kpre[wid] + __popc(s.kw[wid] & low);
            if (pos < MAXDET) {
                unsigned long long key = s.skey[tid];
                float sc = __uint_as_float((~(unsigned)(key >> 32)) & 0x7FFFFFFFu);
                float4 bx = s.sbox[tid];
                int base = (b * MAXDET + pos) * 4;
                oB[base + 0] = bx.x; oB[base + 1] = bx.y;
                oB[base + 2] = bx.z; oB[base + 3] = bx.w;
                oS[b * MAXDET + pos] = sc;
                oL[b * MAXDET + pos] = (float)(lab + 1);
                oK[b * MAXDET + pos] = 1.0f;
            }
        }
        return;
    }

    // ================= FALLBACK: full bitonic sort + warp NMS =================
    #pragma unroll 1
    for (int k = 2; k <= MM; k <<= 1) {
        #pragma unroll 1
        for (int j = k >> 1; j > 0; j >>= 1) {
            #pragma unroll
            for (int q = 0; q < 2; q++) {
                int p = tid + q * 1024;
                int i = ((p & ~(j - 1)) << 1) | (p & (j - 1));
                int l = i | j;
                bool up = ((i & k) == 0);
                unsigned long long a = s.key[i], c = s.key[l];
                if ((a > c) == up) { s.key[i] = c; s.key[l] = a; }
            }
            __syncthreads();
        }
    }
    for (int t = tid; t < PRE; t += 1024) {
        int idx = (int)(unsigned)s.key[t];
        s.sbox[t] = g_box[b][idx];
    }
    __syncthreads();

    if (tid < 32) {
        int cnt = 0;
        for (int t = 0; t < MM; t++) {
            unsigned long long key = s.key[t];
            unsigned hi = (unsigned)(key >> 32);
            if (hi == 0xFFFFFFFFu) break;
            int idx = (int)(unsigned)key;
            int lb = idx & 1;
            float sc = __uint_as_float((~hi) & 0x7FFFFFFFu);
            float4 bc = (t < PRE) ? s.sbox[t] : g_box[b][idx];
            float area = (bc.z - bc.x) * (bc.w - bc.y);
            bool sup = false;
            for (int j = lane; j < cnt; j += 32) {
                if (s.klab[j] == lb) {
                    float4 kb = s.kbox[j];
                    float iw = fminf(bc.z, kb.z) - fmaxf(bc.x, kb.x);
                    float ih = fminf(bc.w, kb.w) - fmaxf(bc.y, kb.y);
                    iw = fmaxf(iw, 0.0f); ih = fmaxf(ih, 0.0f);
                    float inter = iw * ih;
                    if (2.0f * inter > area + s.karea[j] - inter + 1e-7f) sup = true;
                }
            }
            if (__ballot_sync(FULL, sup) == 0u) {
                if (lane == 0) {
                    s.kbox[cnt] = bc; s.karea[cnt] = area;
                    s.kscore[cnt] = sc; s.klab[cnt] = lb;
                }
                cnt++;
                __syncwarp();
                if (cnt == MAXDET) break;
            }
        }
        if (lane == 0) s.s_cnt = cnt;
    }
    __syncthreads();

    int cnt = s.s_cnt;
    for (int j = tid; j < MAXDET; j += 1024) {
        bool k = (j < cnt);
        float4 bc = k ? s.kbox[j] : make_float4(0.f, 0.f, 0.f, 0.f);
        int base = (b * MAXDET + j) * 4;
        oB[base + 0] = bc.x; oB[base + 1] = bc.y;
        oB[base + 2] = bc.z; oB[base + 3] = bc.w;
        oS[b * MAXDET + j] = k ? s.kscore[j] : 0.0f;
        oL[b * MAXDET + j] = k ? (float)(s.klab[j] + 1) : 0.0f;
        oK[b * MAXDET + j] = k ? 1.0f : 0.0f;
    }
}

// ---------------------------------------------------------------------------
extern "C" void kernel_launch(void* const* d_in, const int* in_sizes, int n_in,
                              void* d_out, int out_size) {
    const float* logits = nullptr;
    const float* reg    = nullptr;
    const float* props  = nullptr;
    const void*  dims[2] = {nullptr, nullptr};
    int nd = 0;
    for (int i = 0; i < n_in; i++) {
        int sz = in_sizes[i];
        if      (sz == BD * NP * 3)  logits = (const float*)d_in[i];
        else if (sz == BD * NP * 12) reg    = (const float*)d_in[i];
        else if (sz == BD * NP * 4)  props  = (const float*)d_in[i];
        else if (sz == 1 && nd < 2)  dims[nd++] = d_in[i];
    }

    const int smem_bytes = (int)sizeof(SM);
    cudaFuncSetAttribute(fused_kernel, cudaFuncAttributeMaxDynamicSharedMemorySize, smem_bytes);
    fused_kernel<<<BD, 1024, smem_bytes>>>(logits, reg, props, dims[0], dims[1], (float*)d_out);
}

// round 8
// speedup vs baseline: 4.9065x; 1.6745x over previous
#include <cuda_runtime.h>

// Problem shapes (fixed by setup_inputs): B=4, N=2048, C=3
#define BD 4
#define NP 2048
#define MM 4096          // N * (C-1) candidates per image
#define MAXDET 100
#define CAP 512          // max selected candidates (global prefix)
#define PCCAP 256        // max per-class selected candidates
#define TSEL 160         // selection target (> ~110 consumed by NMS)
#define PRE 512          // fallback: sorted boxes pre-gathered
#define HB0 0x400        // first histogram bin (12-bit key bin space)
#define NHB 64           // histogram bins

struct __align__(16) SM {
    float4 box[MM];                   // all candidate boxes (smem-resident)
    unsigned long long key[MM];       // all 4096 keys (intact for fallback)
    unsigned long long selkey[CAP];   // selected (unordered, padded)
    unsigned long long skey[CAP];     // selected (sorted)
    float4 sbox[CAP];                 // boxes in global sorted order
    float4 cbox[2][PCCAP];            // per-class boxes (score order, zero-padded)
    float4 kbox[MAXDET];              // fallback kept boxes
    unsigned int hist[NHB];
    unsigned int mask[2][PCCAP][8];   // per-class suppression bitmask
    float carea[2][PCCAP];
    unsigned int labw[16];            // label-1 bit per global rank
    unsigned int pre1[16];            // excl prefix of label-1 popcounts
    unsigned int kbits[2][8];         // per-class keep bits
    unsigned int kw[16];              // global keep bits
    unsigned int kpre[16];            // excl prefix of keep popcounts
    unsigned short clsrank[CAP];
    float karea[MAXDET]; float kscore[MAXDET]; int klab[MAXDET];
    int cn[2];
    int c1_rel, n_valid, n_sel, fb, s_cnt, cnt_sel, kept_total;
};

__device__ __forceinline__ float read_dim(const void* p) {
    if (p == nullptr) return 800.0f;
    int v = *(const int*)p;
    if (v > 0 && v < 1000000) return (float)v;   // stored as int32
    return *(const float*)p;                      // stored as float32
}

__device__ __forceinline__ int hbin_of(unsigned long long k) {
    int b12 = (int)(k >> 52);
    return min(max(b12 - HB0, 0), NHB - 1);
}

__global__ __launch_bounds__(1024, 1)
void fused_kernel(const float* __restrict__ logits,
                  const float* __restrict__ reg,
                  const float* __restrict__ props,
                  const void* ph, const void* pw,
                  float* __restrict__ out) {
    extern __shared__ unsigned char smem_raw[];
    SM& s = *reinterpret_cast<SM*>(smem_raw);

    const int b    = blockIdx.x;
    const int tid  = threadIdx.x;
    const int lane = tid & 31;
    const int wid  = tid >> 5;
    const unsigned FULL = 0xFFFFFFFFu;
    const float H = read_dim(ph), W = read_dim(pw);
    const float SCL = 4.135166556742356f;   // ln(1000/16)

    if (tid == 0) { s.fb = 0; s.cnt_sel = 0; s.n_sel = 0; }
    if (tid < NHB) s.hist[tid] = 0;
    __syncthreads();   // hist must be zero before Phase A's fused atomics

    // ---- Phase A: prep (softmax + decode + clip + key + fused histogram) ----
    for (int p = tid; p < NP; p += 1024) {
        const float* L = logits + (b * NP + p) * 3;
        float l0 = L[0], l1 = L[1], l2 = L[2];
        float mx = fmaxf(l0, fmaxf(l1, l2));
        float e0 = __expf(l0 - mx), e1 = __expf(l1 - mx), e2 = __expf(l2 - mx);
        float inv = __fdividef(1.0f, e0 + e1 + e2);
        float sc1 = e1 * inv, sc2 = e2 * inv;

        const float4 P = *(const float4*)(props + (b * NP + p) * 4);
        float pw_ = P.z - P.x, ph_ = P.w - P.y;
        float cx = P.x + 0.5f * pw_, cy = P.y + 0.5f * ph_;

        const float4 R1 = *(const float4*)(reg + (b * NP + p) * 12 + 4);
        const float4 R2 = *(const float4*)(reg + (b * NP + p) * 12 + 8);

        #pragma unroll
        for (int cc = 0; cc < 2; cc++) {
            float4 R = cc ? R2 : R1;
            float sc = cc ? sc2 : sc1;
            int   m  = 2 * p + cc;
            float dx = R.x * 0.1f;
            float dy = R.y * 0.1f;
            float dw = fminf(R.z * 0.2f, SCL);
            float dh = fminf(R.w * 0.2f, SCL);
            float pcx = dx * pw_ + cx;
            float pcy = dy * ph_ + cy;
            float nw  = __expf(dw) * pw_;
            float nh  = __expf(dh) * ph_;
            float x1 = fminf(fmaxf(pcx - 0.5f * nw, 0.0f), W);
            float y1 = fminf(fmaxf(pcy - 0.5f * nh, 0.0f), H);
            float x2 = fminf(fmaxf(pcx + 0.5f * nw, 0.0f), W);
            float y2 = fminf(fmaxf(pcy + 0.5f * nh, 0.0f), H);
            bool valid = (sc > 0.05f) && ((x2 - x1) >= 0.01f) && ((y2 - y1) >= 0.01f);
            s.box[m] = make_float4(x1, y1, x2, y2);
            unsigned long long key;
            if (valid) {
                unsigned mono = __float_as_uint(sc) | 0x80000000u;    // sc > 0
                key = (((unsigned long long)(~mono)) << 32) | (unsigned)m;
                atomicAdd(&s.hist[hbin_of(key)], 1u);
            } else {
                key = 0xFFFFFFFF00000000ull | (unsigned)m;            // bin 0xFFF
            }
            s.key[m] = key;
        }
    }
    __syncthreads();

    // ---- Phase B: single-warp cutoff scan over 64 bins ----
    if (tid < 32) {   // 2 bins per lane, ordered scan
        unsigned v0 = s.hist[2 * lane], v1 = s.hist[2 * lane + 1];
        unsigned lsum = v0 + v1;
        unsigned inc = lsum;
        #pragma unroll
        for (int o = 1; o < 32; o <<= 1) {
            unsigned x = __shfl_up_sync(FULL, inc, o);
            if (lane >= o) inc += x;
        }
        unsigned excl = inc - lsum;
        unsigned total = __shfl_sync(FULL, inc, 31);
        bool cross = ((int)excl < TSEL) && ((int)(excl + lsum) >= TSEL);
        unsigned mb = __ballot_sync(FULL, cross);
        if (lane == 0) s.n_valid = (int)total;
        if (mb == 0) {
            if (lane == 0) { s.c1_rel = NHB - 1; s.n_sel = (int)total; }  // take all valid
        } else {
            int src = __ffs(mb) - 1;
            if (lane == src) {
                int rel, incl;
                if ((int)excl + (int)v0 >= TSEL) { rel = 2 * src;     incl = (int)excl + (int)v0; }
                else                             { rel = 2 * src + 1; incl = (int)excl + (int)lsum; }
                if (incl > CAP) s.fb = 1;                      // fat cutoff bin -> fallback
                else            { s.c1_rel = rel; s.n_sel = incl; }
            }
        }
    }
    __syncthreads();

    const int n_sel = s.n_sel;
    const int c1r   = s.c1_rel;

    // ---- compact selected keys (unordered) ----
    if (!s.fb) {
        for (int m = tid; m < MM; m += 1024) {
            unsigned long long k = s.key[m];
            if ((int)(k >> 52) != 0xFFF && hbin_of(k) <= c1r) {
                int pos = atomicAdd(&s.cnt_sel, 1);
                if (pos < CAP) s.selkey[pos] = k;
            }
        }
    }
    __syncthreads();
    for (int t = tid; t < CAP; t += 1024)
        if (t >= n_sel) s.selkey[t] = 0xFFFFFFFFFFFFF000ull + (unsigned)t;
    __syncthreads();

    // ---- Phase C: rank sort, 2 threads per element (pairs are warp-aligned) ----
    const int n_pad = (n_sel + 31) & ~31;
    if (tid < 2 * n_pad) {
        int e = tid >> 1, half = tid & 1;
        unsigned long long k = s.selkey[e];
        int j0 = half ? (n_pad >> 1) : 0;
        int j1 = half ? n_pad : (n_pad >> 1);
        int r = 0;
        #pragma unroll 8
        for (int j = j0; j < j1; j++) r += (s.selkey[j] < k);
        r += __shfl_xor_sync(FULL, r, 1);
        if (!half) s.skey[r] = k;
    }
    __syncthreads();

    // ---- Phase D: gather + per-class partition ----
    bool act = false; int lab = 0; float4 bb = make_float4(0.f, 0.f, 0.f, 0.f);
    if (tid < 512) {
        act = (tid < n_sel);
        if (act) {
            int idx = (int)(unsigned)s.skey[tid];
            lab = idx & 1;
            bb = s.box[idx];
            s.sbox[tid] = bb;
        }
        unsigned bal = __ballot_sync(FULL, act && lab);
        if (lane == 0) s.labw[wid] = bal;
    }
    __syncthreads();
    if (tid < 32) {
        unsigned c = (lane < 16) ? __popc(s.labw[lane]) : 0;
        unsigned inc = c;
        #pragma unroll
        for (int o = 1; o < 32; o <<= 1) {
            unsigned x = __shfl_up_sync(FULL, inc, o);
            if (lane >= o) inc += x;
        }
        if (lane < 16) s.pre1[lane] = inc - c;
        unsigned cn1 = __shfl_sync(FULL, inc, 15);
        if (lane == 0) {
            s.cn[1] = (int)cn1;
            s.cn[0] = n_sel - (int)cn1;
            if (s.cn[0] > PCCAP || s.cn[1] > PCCAP) s.fb = 1;
        }
    }
    __syncthreads();
    if (tid < 512 && act) {
        unsigned low = (1u << lane) - 1u;
        int c1below = (int)s.pre1[wid] + __popc(s.labw[wid] & low);
        int r = lab ? c1below : (tid - c1below);
        s.clsrank[tid] = (unsigned short)r;
        if (r < PCCAP) {
            s.cbox[lab][r]  = bb;
            s.carea[lab][r] = (bb.z - bb.x) * (bb.w - bb.y);
        }
    }
    // zero-pad per-class tails (disjoint addresses from scatter above)
    for (int u = tid; u < 2 * PCCAP; u += 1024) {
        int c = u >> 8, r = u & (PCCAP - 1);
        if (r >= min(s.cn[c], PCCAP)) {
            s.cbox[c][r] = make_float4(0.f, 0.f, 0.f, 0.f);
            s.carea[c][r] = 0.f;
        }
    }
    __syncthreads();

    // ---- Phase E: per-class suppression bitmask ----
    for (int u = tid; u < 2 * PCCAP * 8; u += 1024) {
        int c = u >> 11, i = (u >> 3) & (PCCAP - 1), w = u & 7;
        unsigned bits = 0;
        int nc_ = s.cn[c];
        if (i < nc_ && w >= (i >> 5) && (w << 5) < nc_) {
            float4 bi = s.cbox[c][i];
            float  ai = s.carea[c][i];
            int j0 = w << 5;
            #pragma unroll
            for (int l = 0; l < 32; l++) {
                int j = j0 + l;
                float4 bj = s.cbox[c][j];
                float iw = fminf(bi.z, bj.z) - fmaxf(bi.x, bj.x);
                float ih = fminf(bi.w, bj.w) - fmaxf(bi.y, bj.y);
                iw = fmaxf(iw, 0.0f); ih = fmaxf(ih, 0.0f);
                float inter = iw * ih;
                bool sp = (j > i) && (2.0f * inter > ai + s.carea[c][j] - inter + 1e-7f);
                bits |= (sp ? (1u << l) : 0u);
            }
        }
        s.mask[c][i][w] = bits;
    }
    __syncthreads();

    // ---- Phase F: per-class greedy resolution (warps 0 and 1 in parallel) ----
    if (wid < 2) {
        int c = wid;
        int nc_ = min(s.cn[c], PCCAP);
        unsigned removed = 0, kb = 0;
        int cnt = 0;
        for (int i = 0; i < nc_; i++) {
            unsigned rw = __shfl_sync(FULL, removed, i >> 5);
            if (!((rw >> (i & 31)) & 1u)) {
                if (lane == (i >> 5)) kb |= 1u << (i & 31);
                cnt++;
                if (lane < 8) removed |= s.mask[c][i][lane];
                if (cnt == MAXDET) break;
            }
        }
        if (lane < 8) s.kbits[c][lane] = kb;
    }
    __syncthreads();

    // ---- Phase G: merge kept flags back to global order ----
    bool kflag = false;
    if (tid < 512) {
        if (act) {
            int r = s.clsrank[tid];
            kflag = (s.kbits[lab][r >> 5] >> (r & 31)) & 1u;
        }
        unsigned bal = __ballot_sync(FULL, kflag);
        if (lane == 0) s.kw[wid] = bal;
    }
    __syncthreads();
    if (tid < 32) {
        unsigned c = (lane < 16) ? __popc(s.kw[lane]) : 0;
        unsigned inc = c;
        #pragma unroll
        for (int o = 1; o < 32; o <<= 1) {
            unsigned x = __shfl_up_sync(FULL, inc, o);
            if (lane >= o) inc += x;
        }
        if (lane < 16) s.kpre[lane] = inc - c;
        unsigned tot = __shfl_sync(FULL, inc, 15);
        if (lane == 0) {
            s.kept_total = (int)tot;
            if ((int)tot < MAXDET && s.n_valid > n_sel) s.fb = 1;  // prefix exhausted
        }
    }
    __syncthreads();

    float* oB = out;                              // [B,100,4]
    float* oS = out + BD * MAXDET * 4;            // [B,100]
    float* oL = oS + BD * MAXDET;                 // [B,100]
    float* oK = oL + BD * MAXDET;                 // [B,100]

    if (!s.fb) {
        for (int j = tid; j < MAXDET; j += 1024) {
            int base = (b * MAXDET + j) * 4;
            oB[base + 0] = 0.f; oB[base + 1] = 0.f; oB[base + 2] = 0.f; oB[base + 3] = 0.f;
            oS[b * MAXDET + j] = 0.f;
            oL[b * MAXDET + j] = 0.f;
            oK[b * MAXDET + j] = 0.f;
        }
        __syncthreads();
        if (tid < 512 && kflag) {
            unsigned low = (1u << lane) - 1u;
            int pos = (int)s.kpre[wid] + __popc(s.kw[wid] & low);
            if (pos < MAXDET) {
                unsigned long long key = s.skey[tid];
                float sc = __uint_as_float((~(unsigned)(key >> 32)) & 0x7FFFFFFFu);
                float4 bx = s.sbox[tid];
                int base = (b * MAXDET + pos) * 4;
                oB[base + 0] = bx.x; oB[base + 1] = bx.y;
                oB[base + 2] = bx.z; oB[base + 3] = bx.w;
                oS[b * MAXDET + pos] = sc;
                oL[b * MAXDET + pos] = (float)(lab + 1);
                oK[b * MAXDET + pos] = 1.0f;
            }
        }
        return;
    }

    // ================= FALLBACK: full bitonic sort + warp NMS =================
    #pragma unroll 1
    for (int k = 2; k <= MM; k <<= 1) {
        #pragma unroll 1
        for (int j = k >> 1; j > 0; j >>= 1) {
            #pragma unroll
            for (int q = 0; q < 2; q++) {
                int p = tid + q * 1024;
                int i = ((p & ~(j - 1)) << 1) | (p & (j - 1));
                int l = i | j;
                bool up = ((i & k) == 0);
                unsigned long long a = s.key[i], c = s.key[l];
                if ((a > c) == up) { s.key[i] = c; s.key[l] = a; }
            }
            __syncthreads();
        }
    }
    for (int t = tid; t < PRE; t += 1024) {
        int idx = (int)(unsigned)s.key[t];
        s.sbox[t] = s.box[idx];
    }
    __syncthreads();

    if (tid < 32) {
        int cnt = 0;
        for (int t = 0; t < MM; t++) {
            unsigned long long key = s.key[t];
            unsigned hi = (unsigned)(key >> 32);
            if (hi == 0xFFFFFFFFu) break;
            int idx = (int)(unsigned)key;
            int lb = idx & 1;
            float sc = __uint_as_float((~hi) & 0x7FFFFFFFu);
            float4 bc = (t < PRE) ? s.sbox[t] : s.box[idx];
            float area = (bc.z - bc.x) * (bc.w - bc.y);
            bool sup = false;
            for (int j = lane; j < cnt; j += 32) {
                if (s.klab[j] == lb) {
                    float4 kb = s.kbox[j];
                    float iw = fminf(bc.z, kb.z) - fmaxf(bc.x, kb.x);
                    float ih = fminf(bc.w, kb.w) - fmaxf(bc.y, kb.y);
                    iw = fmaxf(iw, 0.0f); ih = fmaxf(ih, 0.0f);
                    float inter = iw * ih;
                    if (2.0f * inter > area + s.karea[j] - inter + 1e-7f) sup = true;
                }
            }
            if (__ballot_sync(FULL, sup) == 0u) {
                if (lane == 0) {
                    s.kbox[cnt] = bc; s.karea[cnt] = area;
                    s.kscore[cnt] = sc; s.klab[cnt] = lb;
                }
                cnt++;
                __syncwarp();
                if (cnt == MAXDET) break;
            }
        }
        if (lane == 0) s.s_cnt = cnt;
    }
    __syncthreads();

    int cnt = s.s_cnt;
    for (int j = tid; j < MAXDET; j += 1024) {
        bool k = (j < cnt);
        float4 bc = k ? s.kbox[j] : make_float4(0.f, 0.f, 0.f, 0.f);
        int base = (b * MAXDET + j) * 4;
        oB[base + 0] = bc.x; oB[base + 1] = bc.y;
        oB[base + 2] = bc.z; oB[base + 3] = bc.w;
        oS[b * MAXDET + j] = k ? s.kscore[j] : 0.0f;
        oL[b * MAXDET + j] = k ? (float)(s.klab[j] + 1) : 0.0f;
        oK[b * MAXDET + j] = k ? 1.0f : 0.0f;
    }
}

// ---------------------------------------------------------------------------
extern "C" void kernel_launch(void* const* d_in, const int* in_sizes, int n_in,
                              void* d_out, int out_size) {
    const float* logits = nullptr;
    const float* reg    = nullptr;
    const float* props  = nullptr;
    const void*  dims[2] = {nullptr, nullptr};
    int nd = 0;
    for (int i = 0; i < n_in; i++) {
        int sz = in_sizes[i];
        if      (sz == BD * NP * 3)  logits = (const float*)d_in[i];
        else if (sz == BD * NP * 12) reg    = (const float*)d_in[i];
        else if (sz == BD * NP * 4)  props  = (const float*)d_in[i];
        else if (sz == 1 && nd < 2)  dims[nd++] = d_in[i];
    }

    const int smem_bytes = (int)sizeof(SM);
    cudaFuncSetAttribute(fused_kernel, cudaFuncAttributeMaxDynamicSharedMemorySize, smem_bytes);
    fused_kernel<<<BD, 1024, smem_bytes>>>(logits, reg, props, dims[0], dims[1], (float*)d_out);
}